// round 16
// baseline (speedup 1.0000x reference)
#include <cuda_runtime.h>

#define BB 16
#define TT 8192
#define HH 256
#define LCH 32
#define KCH 256           // TT/LCH
#define MST 132           // matrix storage: 11 rows x 12 floats (padded)
#define NBLK 16           // em blocks per batch (TT/512)
#define CWPB 8            // chunks (warps) per chunk-kernel block

typedef unsigned long long ull;

// Scratch (device globals — no allocation allowed)
__device__ __align__(16) float g_eem[(size_t)BB*TT*12];   // per token: ee[0..10], emmax
__device__ __align__(16) float g_M [(size_t)BB*KCH*MST];  // chunk transfer matrices
__device__ __align__(16) float g_a0[BB*12];               // ee at t=0 per batch
__device__ float g_numpart[BB*NBLK];
__device__ float g_denpart[BB*NBLK];
__device__ int   g_exps[BB*KCH];

// ---- packed f32x2 helpers (exact fp32 semantics) ----
__device__ __forceinline__ ull pk2(float lo, float hi){ ull r; asm("mov.b64 %0, {%1,%2};" : "=l"(r) : "f"(lo), "f"(hi)); return r; }
__device__ __forceinline__ void upk2(float &lo, float &hi, ull v){ asm("mov.b64 {%0,%1}, %2;" : "=f"(lo), "=f"(hi) : "l"(v)); }
__device__ __forceinline__ ull ffma2(ull a, ull b, ull c){ ull d; asm("fma.rn.f32x2 %0, %1, %2, %3;" : "=l"(d) : "l"(a), "l"(b), "l"(c)); return d; }

// C[i][j] = sum_k A[i][k]*B[k][j]; rows padded to 12 floats
__device__ __forceinline__ float mm11(const float* A, const float* Bm, int i, int j){
    float4 r0 = *(const float4*)&A[i*12];
    float4 r1 = *(const float4*)&A[i*12+4];
    float4 r2 = *(const float4*)&A[i*12+8];
    float s =        r0.x*Bm[0*12+j];
    s = fmaf(r0.y, Bm[1*12+j], s);
    s = fmaf(r0.z, Bm[2*12+j], s);
    s = fmaf(r0.w, Bm[3*12+j], s);
    s = fmaf(r1.x, Bm[4*12+j], s);
    s = fmaf(r1.y, Bm[5*12+j], s);
    s = fmaf(r1.z, Bm[6*12+j], s);
    s = fmaf(r1.w, Bm[7*12+j], s);
    s = fmaf(r2.x, Bm[8*12+j], s);
    s = fmaf(r2.y, Bm[9*12+j], s);
    s = fmaf(r2.z, Bm[10*12+j], s);
    return s;
}
__device__ __forceinline__ void storeP(float* C, int i, int j, float v){
    C[i*12+j] = v;
    if (j == 0) C[i*12+11] = 0.f;
}

// ---------------------------------------------------------------------------
// per-token epilogue: normalized exp-emissions + numerator contribution
// ---------------------------------------------------------------------------
__device__ __forceinline__ void process_token(
    int t, int b, int len,
    const float em[11],
    const float* __restrict__ start_tr, const float* __restrict__ trans,
    const float* __restrict__ end_tr, const int* __restrict__ labels,
    float& numc, float& msks)
{
    float mx = em[0];
    #pragma unroll
    for (int q = 1; q < 11; q++) mx = fmaxf(mx, em[q]);
    float ee[11];
    #pragma unroll
    for (int q = 0; q < 11; q++) ee[q] = __expf(em[q] - mx);

    float4* d4 = (float4*)&g_eem[((size_t)b*TT + t) * 12];
    d4[0] = make_float4(ee[0],ee[1],ee[2],ee[3]);
    d4[1] = make_float4(ee[4],ee[5],ee[6],ee[7]);
    d4[2] = make_float4(ee[8],ee[9],ee[10],mx);

    if (t < len) msks += mx;

    int lab = labels[(size_t)b*TT + t];
    int tag = (lab == -100) ? 0 : lab;
    float emt = em[0];
    #pragma unroll
    for (int q = 1; q < 11; q++) if (tag == q) emt = em[q];

    if (t == 0){
        numc += start_tr[tag] + emt;
        float4* g4 = (float4*)&g_a0[b*12];
        g4[0] = make_float4(ee[0],ee[1],ee[2],ee[3]);
        g4[1] = make_float4(ee[4],ee[5],ee[6],ee[7]);
        g4[2] = make_float4(ee[8],ee[9],ee[10],0.f);
    } else if (t < len){
        int labp = labels[(size_t)b*TT + t - 1];
        int tagp = (labp == -100) ? 0 : labp;
        numc += trans[tagp*11 + tag] + emt;
    }
    if (t == len - 1) numc += end_tr[tag];
}

// ---------------------------------------------------------------------------
// Kernel 1: emissions. Grid (NBLK, BB), 128 thr, 4 tokens/thread. (R15-proven)
// ---------------------------------------------------------------------------
__global__ void __launch_bounds__(128) em_kernel(
    const float* __restrict__ seq,
    const float* __restrict__ Wenc,
    const float* __restrict__ benc,
    const float* __restrict__ Wemit,
    const float* __restrict__ bemit,
    const float* __restrict__ start_tr,
    const float* __restrict__ trans,
    const float* __restrict__ end_tr,
    const int* __restrict__ lengths,
    const int* __restrict__ labels,
    float* __restrict__ out)
{
    __shared__ float4     sEnc[HH];       // (w0,w1,w2,w3)
    __shared__ ulonglong2 sEmA[HH];       // (e01, e23)
    __shared__ ulonglong2 sEmB[HH];       // (e45, e67)
    __shared__ ulonglong2 sEmC[HH];       // (e89, (e10, bn))
    __shared__ float      sRedN[4], sRedD[4];

    int tid = threadIdx.x;
    int b = blockIdx.y;
    int t0 = blockIdx.x * 512;
    int len = lengths[b];

    if (blockIdx.x == 0 && b == 0 && tid == 0) out[0] = 0.f;

    for (int h = tid; h < HH; h += 128){
        sEnc[h] = make_float4(Wenc[h], Wenc[HH+h], Wenc[2*HH+h], Wenc[3*HH+h]);
        float e[11];
        #pragma unroll
        for (int q = 0; q < 11; q++) e[q] = Wemit[h*11+q];
        sEmA[h] = make_ulonglong2(pk2(e[0],e[1]), pk2(e[2],e[3]));
        sEmB[h] = make_ulonglong2(pk2(e[4],e[5]), pk2(e[6],e[7]));
        sEmC[h] = make_ulonglong2(pk2(e[8],e[9]), pk2(e[10], benc[h]));
    }
    __syncthreads();

    int ta = t0 + tid;                // +0,+128,+256,+384
    const float4* sq = (const float4*)seq + (size_t)b*TT;
    float4 x0 = sq[ta], x1 = sq[ta+128], x2 = sq[ta+256], x3 = sq[ta+384];

    ull b01 = pk2(bemit[0],bemit[1]);
    ull b23 = pk2(bemit[2],bemit[3]);
    ull b45 = pk2(bemit[4],bemit[5]);
    ull b67 = pk2(bemit[6],bemit[7]);
    ull b89 = pk2(bemit[8],bemit[9]);
    float b10 = bemit[10];

    ull a0[5] = {b01,b23,b45,b67,b89};
    ull a1[5] = {b01,b23,b45,b67,b89};
    ull a2[5] = {b01,b23,b45,b67,b89};
    ull a3[5] = {b01,b23,b45,b67,b89};
    ull aX01 = pk2(b10,b10), aX23 = pk2(b10,b10);

    #pragma unroll 2
    for (int h = 0; h < HH; h++){
        float4 w = sEnc[h];
        ulonglong2 eA = sEmA[h];
        ulonglong2 eB = sEmB[h];
        ulonglong2 eC = sEmC[h];
        float e10, bn; upk2(e10, bn, eC.y);
        ull e89 = eC.x;
        ull eXX = pk2(e10, e10);

        float hd0 = fmaxf(fmaf(x0.x,w.x,fmaf(x0.y,w.y,fmaf(x0.z,w.z,fmaf(x0.w,w.w,bn)))), 0.f);
        float hd1 = fmaxf(fmaf(x1.x,w.x,fmaf(x1.y,w.y,fmaf(x1.z,w.z,fmaf(x1.w,w.w,bn)))), 0.f);
        float hd2 = fmaxf(fmaf(x2.x,w.x,fmaf(x2.y,w.y,fmaf(x2.z,w.z,fmaf(x2.w,w.w,bn)))), 0.f);
        float hd3 = fmaxf(fmaf(x3.x,w.x,fmaf(x3.y,w.y,fmaf(x3.z,w.z,fmaf(x3.w,w.w,bn)))), 0.f);

        ull p0 = pk2(hd0,hd0), p1 = pk2(hd1,hd1), p2 = pk2(hd2,hd2), p3 = pk2(hd3,hd3);

        a0[0]=ffma2(p0,eA.x,a0[0]); a0[1]=ffma2(p0,eA.y,a0[1]); a0[2]=ffma2(p0,eB.x,a0[2]); a0[3]=ffma2(p0,eB.y,a0[3]); a0[4]=ffma2(p0,e89,a0[4]);
        a1[0]=ffma2(p1,eA.x,a1[0]); a1[1]=ffma2(p1,eA.y,a1[1]); a1[2]=ffma2(p1,eB.x,a1[2]); a1[3]=ffma2(p1,eB.y,a1[3]); a1[4]=ffma2(p1,e89,a1[4]);
        a2[0]=ffma2(p2,eA.x,a2[0]); a2[1]=ffma2(p2,eA.y,a2[1]); a2[2]=ffma2(p2,eB.x,a2[2]); a2[3]=ffma2(p2,eB.y,a2[3]); a2[4]=ffma2(p2,e89,a2[4]);
        a3[0]=ffma2(p3,eA.x,a3[0]); a3[1]=ffma2(p3,eA.y,a3[1]); a3[2]=ffma2(p3,eB.x,a3[2]); a3[3]=ffma2(p3,eB.y,a3[3]); a3[4]=ffma2(p3,e89,a3[4]);

        aX01 = ffma2(pk2(hd0,hd1), eXX, aX01);
        aX23 = ffma2(pk2(hd2,hd3), eXX, aX23);
    }

    float x10a, x10b, x10c, x10d;
    upk2(x10a, x10b, aX01);
    upk2(x10c, x10d, aX23);

    float numc = 0.f, msks = 0.f;
    {
        float em[11];
        upk2(em[0],em[1],a0[0]); upk2(em[2],em[3],a0[1]); upk2(em[4],em[5],a0[2]);
        upk2(em[6],em[7],a0[3]); upk2(em[8],em[9],a0[4]); em[10]=x10a;
        process_token(ta, b, len, em, start_tr, trans, end_tr, labels, numc, msks);
    }
    {
        float em[11];
        upk2(em[0],em[1],a1[0]); upk2(em[2],em[3],a1[1]); upk2(em[4],em[5],a1[2]);
        upk2(em[6],em[7],a1[3]); upk2(em[8],em[9],a1[4]); em[10]=x10b;
        process_token(ta+128, b, len, em, start_tr, trans, end_tr, labels, numc, msks);
    }
    {
        float em[11];
        upk2(em[0],em[1],a2[0]); upk2(em[2],em[3],a2[1]); upk2(em[4],em[5],a2[2]);
        upk2(em[6],em[7],a2[3]); upk2(em[8],em[9],a2[4]); em[10]=x10c;
        process_token(ta+256, b, len, em, start_tr, trans, end_tr, labels, numc, msks);
    }
    {
        float em[11];
        upk2(em[0],em[1],a3[0]); upk2(em[2],em[3],a3[1]); upk2(em[4],em[5],a3[2]);
        upk2(em[6],em[7],a3[3]); upk2(em[8],em[9],a3[4]); em[10]=x10d;
        process_token(ta+384, b, len, em, start_tr, trans, end_tr, labels, numc, msks);
    }

    #pragma unroll
    for (int o = 16; o > 0; o >>= 1){
        numc += __shfl_xor_sync(0xffffffffu, numc, o);
        msks += __shfl_xor_sync(0xffffffffu, msks, o);
    }
    if ((tid & 31) == 0){ sRedN[tid >> 5] = numc; sRedD[tid >> 5] = msks; }
    __syncthreads();
    if (tid == 0){
        g_numpart[b*NBLK + blockIdx.x] = sRedN[0]+sRedN[1]+sRedN[2]+sRedN[3];
        g_denpart[b*NBLK + blockIdx.x] = sRedD[0]+sRedD[1]+sRedD[2]+sRedD[3];
    }
}

// ---------------------------------------------------------------------------
// Kernel 2: warp-per-chunk barrier-free scan (proven R13 code), LCH=32 now.
// Grid (KCH/CWPB, BB) = (32, 16), 256 threads -> 4096 warps.
// ---------------------------------------------------------------------------
__global__ void __launch_bounds__(256) chunk_kernel(
    const float* __restrict__ trans,
    const int* __restrict__ lengths)
{
    __shared__ float sEem[CWPB][LCH*12];   // 12 KB

    int tid = threadIdx.x;
    int w = tid >> 5, l = tid & 31;
    int b = blockIdx.y;
    int c = blockIdx.x * CWPB + w;
    int t0 = c * LCH;
    int len = lengths[b];

    {
        const float4* src = (const float4*)&g_eem[((size_t)b*TT + blockIdx.x*CWPB*LCH) * 12];
        float4* dst = (float4*)&sEem[0][0];
        for (int q = tid; q < CWPB*LCH*3; q += 256) dst[q] = src[q];
    }
    __syncthreads();

    int i = l % 11;
    int h = l / 11;          // 0 or 1 active; 2 for lanes 22..31
    bool act = l < 22;
    int hc = act ? h : 0;    // clamp inactive lanes in-bounds
    int j0 = h * 6;

    float Treg[6][11];
    #pragma unroll
    for (int jj = 0; jj < 6; jj++){
        int j = j0 + jj;
        int jcl = (act && j < 11) ? j : 0;
        float flag = (act && j < 11) ? 1.f : 0.f;
        #pragma unroll
        for (int k = 0; k < 11; k++)
            Treg[jj][k] = flag * __expf(trans[k*11 + jcl]);
    }

    float row[11];
    #pragma unroll
    for (int k = 0; k < 11; k++) row[k] = (act && k == i) ? 1.f : 0.f;

    int partner = act ? (h ? l - 11 : l + 11) : l;
    int eacc = 0;
    const float* emm = sEem[w];

    for (int s = 0; s < LCH; s++){
        int t = t0 + s;
        bool valid = (t >= 1) && (t < len);     // warp-uniform
        if (valid){
            float4 A  = *(const float4*)&emm[s*12 + hc*8];
            float2 Bv = *(const float2*)&emm[s*12 + 4 + hc*2];
            float ee[6];
            if (hc == 0){ ee[0]=A.x; ee[1]=A.y; ee[2]=A.z; ee[3]=A.w; ee[4]=Bv.x; ee[5]=Bv.y; }
            else        { ee[0]=Bv.x; ee[1]=Bv.y; ee[2]=A.x; ee[3]=A.y; ee[4]=A.z; ee[5]=A.w; }

            float ns[6];
            #pragma unroll
            for (int jj = 0; jj < 6; jj++){
                float s2 = row[0]*Treg[jj][0];
                #pragma unroll
                for (int k = 1; k < 11; k++) s2 = fmaf(row[k], Treg[jj][k], s2);
                ns[jj] = s2 * ee[jj];
            }
            float other[6];
            #pragma unroll
            for (int q = 0; q < 6; q++) other[q] = __shfl_sync(0xffffffffu, ns[q], partner);
            if (h == 0){
                #pragma unroll
                for (int jj = 0; jj < 6; jj++) row[jj] = ns[jj];
                #pragma unroll
                for (int q = 0; q < 5; q++) row[6+q] = other[q];
            } else if (h == 1){
                #pragma unroll
                for (int q = 0; q < 6; q++) row[q] = other[q];
                #pragma unroll
                for (int jj = 0; jj < 5; jj++) row[6+jj] = ns[jj];
            }
        }
        if ((s & 7) == 7){
            float m = row[0];
            #pragma unroll
            for (int k = 1; k < 11; k++) m = fmaxf(m, row[k]);
            if (m > 0.f){
                int e = 0;
                frexpf(m, &e);
                float sc = exp2f((float)(-e));
                #pragma unroll
                for (int k = 0; k < 11; k++) row[k] *= sc;
                eacc += e;
            }
        }
    }

    int ev = act ? eacc : (-2147483647 - 1);
    #pragma unroll
    for (int o = 16; o > 0; o >>= 1) ev = max(ev, __shfl_xor_sync(0xffffffffu, ev, o));

    if (act){
        float sc = exp2f((float)(eacc - ev));
        size_t base = ((size_t)(b*KCH + c)) * MST + (size_t)i*12;
        if (h == 0){
            #pragma unroll
            for (int jj = 0; jj < 6; jj++) g_M[base + jj] = row[jj] * sc;
        } else {
            #pragma unroll
            for (int jj = 0; jj < 5; jj++) g_M[base + 6 + jj] = row[6+jj] * sc;
            g_M[base + 11] = 0.f;
        }
    }
    if (l == 0) g_exps[b*KCH + c] = ev;
}

// ---------------------------------------------------------------------------
// Kernel 3 (tail): per-batch 8-level tree over 256 chunk matrices in SMEM.
// Grid BB, 512 threads, ~203 KB dynamic smem. (R14 correctness-proven.)
// ---------------------------------------------------------------------------
__global__ void __launch_bounds__(512) tail_kernel(
    const float* __restrict__ start_tr,
    const float* __restrict__ end_tr,
    float* __restrict__ out)
{
    extern __shared__ float dynsm[];
    float* bufA = dynsm;               // capacity 256 matrices
    float* bufB = dynsm + 256*MST;     // capacity 128 matrices
    __shared__ float sRedM[16];
    __shared__ float sNum, sDen;
    __shared__ int   sExp;

    int tid = threadIdx.x;
    int b = blockIdx.x;

    if (tid == 0){ sNum = 0.f; sDen = 0.f; sExp = 0; }
    __syncthreads();

    {
        const float4* src = (const float4*)&g_M[(size_t)b*KCH*MST];
        for (int q = tid; q < KCH*MST/4; q += 512) ((float4*)bufA)[q] = src[q];
    }

    {
        float nacc = 0.f, dacc = 0.f; int eacc = 0;
        if (tid < NBLK){ nacc = g_numpart[b*NBLK + tid]; dacc = g_denpart[b*NBLK + tid]; }
        if (tid < KCH)  eacc = g_exps[b*KCH + tid];
        #pragma unroll
        for (int o = 16; o > 0; o >>= 1){
            nacc += __shfl_xor_sync(0xffffffffu, nacc, o);
            dacc += __shfl_xor_sync(0xffffffffu, dacc, o);
            eacc += __shfl_xor_sync(0xffffffffu, eacc, o);
        }
        if ((tid & 31) == 0 && tid < KCH){
            atomicAdd(&sNum, nacc);
            atomicAdd(&sDen, dacc);
            atomicAdd(&sExp, eacc);
        }
    }
    __syncthreads();

    int unit = tid >> 7, st = tid & 127;
    int i = st / 11, j = st - i*11;
    bool act = st < 121;
    int wiu = st >> 5;

    // L1: 128 products, A -> B
    for (int q = unit; q < 128; q += 4)
        if (act) storeP(&bufB[q*MST], i, j, mm11(&bufA[(2*q)*MST], &bufA[(2*q+1)*MST], i, j));
    __syncthreads();
    // L2: 64, B -> A
    for (int q = unit; q < 64; q += 4)
        if (act) storeP(&bufA[q*MST], i, j, mm11(&bufB[(2*q)*MST], &bufB[(2*q+1)*MST], i, j));
    __syncthreads();
    // L3: 32, A -> B
    for (int q = unit; q < 32; q += 4)
        if (act) storeP(&bufB[q*MST], i, j, mm11(&bufA[(2*q)*MST], &bufA[(2*q+1)*MST], i, j));
    __syncthreads();
    // L4: 16 with pow2 norm, B -> A  (4 rounds)
    #pragma unroll
    for (int r = 0; r < 4; r++){
        int q = r*4 + unit;
        float v = act ? mm11(&bufB[(2*q)*MST], &bufB[(2*q+1)*MST], i, j) : 0.f;
        float m = v;
        #pragma unroll
        for (int o = 16; o > 0; o >>= 1) m = fmaxf(m, __shfl_xor_sync(0xffffffffu, m, o));
        if ((st & 31) == 0) sRedM[unit*4 + wiu] = m;
        __syncthreads();
        float mxv = fmaxf(fmaxf(sRedM[unit*4], sRedM[unit*4+1]), fmaxf(sRedM[unit*4+2], sRedM[unit*4+3]));
        int e = 0; frexpf(mxv, &e);
        if (act) storeP(&bufA[q*MST], i, j, v * exp2f((float)(-e)));
        if (st == 0) atomicAdd(&sExp, e);
        __syncthreads();
    }
    // L5: 8, A -> B
    for (int q = unit; q < 8; q += 4)
        if (act) storeP(&bufB[q*MST], i, j, mm11(&bufA[(2*q)*MST], &bufA[(2*q+1)*MST], i, j));
    __syncthreads();
    // L6: 4, B -> A
    {
        int q = unit;
        if (act) storeP(&bufA[q*MST], i, j, mm11(&bufB[(2*q)*MST], &bufB[(2*q+1)*MST], i, j));
    }
    __syncthreads();
    // L7: 2 with pow2 norm, A -> B (units 0,1)
    {
        bool run = unit < 2;
        float v = (run && act) ? mm11(&bufA[(2*unit)*MST], &bufA[(2*unit+1)*MST], i, j) : 0.f;
        float m = v;
        #pragma unroll
        for (int o = 16; o > 0; o >>= 1) m = fmaxf(m, __shfl_xor_sync(0xffffffffu, m, o));
        if ((st & 31) == 0) sRedM[unit*4 + wiu] = m;
        __syncthreads();
        float mxv = fmaxf(fmaxf(sRedM[unit*4], sRedM[unit*4+1]), fmaxf(sRedM[unit*4+2], sRedM[unit*4+3]));
        int e = 0; frexpf(mxv, &e);
        if (run && act) storeP(&bufB[unit*MST], i, j, v * exp2f((float)(-e)));
        if (run && st == 0) atomicAdd(&sExp, e);
        __syncthreads();
    }
    // L8: final product, B[0]*B[1] -> A[0]
    if (unit == 0 && act)
        storeP(&bufA[0], i, j, mm11(&bufB[0], &bufB[MST], i, j));
    __syncthreads();

    if (tid < 32){
        bool a11 = tid < 11;
        float p0 = a11 ? __expf(start_tr[tid]) * g_a0[b*12 + tid] : 0.f;
        float pf = 0.f;
        #pragma unroll
        for (int k = 0; k < 11; k++){
            float pkv = __shfl_sync(0xffffffffu, p0, k);
            pf = fmaf(pkv, a11 ? bufA[k*12 + tid] : 0.f, pf);
        }
        float vv = a11 ? pf * __expf(end_tr[tid]) : 0.f;
        #pragma unroll
        for (int o = 16; o > 0; o >>= 1) vv += __shfl_xor_sync(0xffffffffu, vv, o);
        if (tid == 0){
            float den = logf(vv) + 0.6931471805599453f * (float)sExp + sDen;
            atomicAdd(out, (den - sNum) * (1.0f / (float)BB));
        }
    }
}

// ---------------------------------------------------------------------------
// Launch
// ---------------------------------------------------------------------------
#define SMEM_TAIL ((256*MST + 128*MST) * 4)

extern "C" void kernel_launch(void* const* d_in, const int* in_sizes, int n_in,
                              void* d_out, int out_size)
{
    const float* seq      = (const float*)d_in[0];
    const float* Wenc     = (const float*)d_in[1];
    const float* benc     = (const float*)d_in[2];
    const float* Wemit    = (const float*)d_in[3];
    const float* bemit    = (const float*)d_in[4];
    const float* start_tr = (const float*)d_in[5];
    const float* trans    = (const float*)d_in[6];
    const float* end_tr   = (const float*)d_in[7];
    const int* lengths    = (const int*)d_in[8];
    const int* labels     = (const int*)d_in[9];
    float* out = (float*)d_out;

    cudaFuncSetAttribute(tail_kernel, cudaFuncAttributeMaxDynamicSharedMemorySize, SMEM_TAIL);

    em_kernel<<<dim3(NBLK, BB), 128>>>(seq, Wenc, benc, Wemit, bemit,
                                       start_tr, trans, end_tr, lengths, labels, out);
    chunk_kernel<<<dim3(KCH/CWPB, BB), 256>>>(trans, lengths);
    tail_kernel<<<BB, 512, SMEM_TAIL>>>(start_tr, end_tr, out);
}

// round 17
// speedup vs baseline: 1.1900x; 1.1900x over previous
#include <cuda_runtime.h>

#define BB 16
#define TT 8192
#define HH 256
#define LCH 64
#define KCH 128           // TT/LCH
#define MST 132           // matrix storage: 11 rows x 12 floats (padded)
#define NBLK 16           // fused blocks per batch (TT/512)
#define CWPB 8            // chunks (warps) per fused block

typedef unsigned long long ull;

// Scratch (device globals — no allocation allowed)
__device__ __align__(16) float g_M [(size_t)BB*KCH*MST];  // chunk transfer matrices
__device__ __align__(16) float g_a0[BB*12];               // ee at t=0 per batch
__device__ float g_numpart[BB*NBLK];
__device__ float g_denpart[BB*NBLK];
__device__ int   g_exps[BB*KCH];

// ---- packed f32x2 helpers (exact fp32 semantics) ----
__device__ __forceinline__ ull pk2(float lo, float hi){ ull r; asm("mov.b64 %0, {%1,%2};" : "=l"(r) : "f"(lo), "f"(hi)); return r; }
__device__ __forceinline__ void upk2(float &lo, float &hi, ull v){ asm("mov.b64 {%0,%1}, %2;" : "=f"(lo), "=f"(hi) : "l"(v)); }
__device__ __forceinline__ ull ffma2(ull a, ull b, ull c){ ull d; asm("fma.rn.f32x2 %0, %1, %2, %3;" : "=l"(d) : "l"(a), "l"(b), "l"(c)); return d; }

// C[i][j] = sum_k A[i][k]*B[k][j]; rows padded to 12 floats
__device__ __forceinline__ float mm11(const float* A, const float* Bm, int i, int j){
    float4 r0 = *(const float4*)&A[i*12];
    float4 r1 = *(const float4*)&A[i*12+4];
    float4 r2 = *(const float4*)&A[i*12+8];
    float s =        r0.x*Bm[0*12+j];
    s = fmaf(r0.y, Bm[1*12+j], s);
    s = fmaf(r0.z, Bm[2*12+j], s);
    s = fmaf(r0.w, Bm[3*12+j], s);
    s = fmaf(r1.x, Bm[4*12+j], s);
    s = fmaf(r1.y, Bm[5*12+j], s);
    s = fmaf(r1.z, Bm[6*12+j], s);
    s = fmaf(r1.w, Bm[7*12+j], s);
    s = fmaf(r2.x, Bm[8*12+j], s);
    s = fmaf(r2.y, Bm[9*12+j], s);
    s = fmaf(r2.z, Bm[10*12+j], s);
    return s;
}
__device__ __forceinline__ void storeP(float* C, int i, int j, float v){
    C[i*12+j] = v;
    if (j == 0) C[i*12+11] = 0.f;
}

// ---------------------------------------------------------------------------
// per-token epilogue: normalized exp-emissions (to SMEM) + numerator contrib
// ---------------------------------------------------------------------------
__device__ __forceinline__ void process_token_sm(
    int t, int trel, int b, int len,
    const float em[11], float* __restrict__ sEem,
    const float* __restrict__ start_tr, const float* __restrict__ trans,
    const float* __restrict__ end_tr, const int* __restrict__ labels,
    float& numc, float& msks)
{
    float mx = em[0];
    #pragma unroll
    for (int q = 1; q < 11; q++) mx = fmaxf(mx, em[q]);
    float ee[11];
    #pragma unroll
    for (int q = 0; q < 11; q++) ee[q] = __expf(em[q] - mx);

    float4* d4 = (float4*)&sEem[trel*12];
    d4[0] = make_float4(ee[0],ee[1],ee[2],ee[3]);
    d4[1] = make_float4(ee[4],ee[5],ee[6],ee[7]);
    d4[2] = make_float4(ee[8],ee[9],ee[10],mx);

    if (t < len) msks += mx;

    int lab = labels[(size_t)b*TT + t];
    int tag = (lab == -100) ? 0 : lab;
    float emt = em[0];
    #pragma unroll
    for (int q = 1; q < 11; q++) if (tag == q) emt = em[q];

    if (t == 0){
        numc += start_tr[tag] + emt;
        float4* g4 = (float4*)&g_a0[b*12];
        g4[0] = make_float4(ee[0],ee[1],ee[2],ee[3]);
        g4[1] = make_float4(ee[4],ee[5],ee[6],ee[7]);
        g4[2] = make_float4(ee[8],ee[9],ee[10],0.f);
    } else if (t < len){
        int labp = labels[(size_t)b*TT + t - 1];
        int tagp = (labp == -100) ? 0 : labp;
        numc += trans[tagp*11 + tag] + emt;
    }
    if (t == len - 1) numc += end_tr[tag];
}

// ---------------------------------------------------------------------------
// Kernel 1 (fused): em phase (2 tokens/thread into SMEM) + warp-autonomous
// chunk scans (8 warps x 64-token chunks). ONE inter-phase barrier.
// Grid (NBLK, BB), 256 threads.
// ---------------------------------------------------------------------------
__global__ void __launch_bounds__(256) fused_kernel(
    const float* __restrict__ seq,
    const float* __restrict__ Wenc,
    const float* __restrict__ benc,
    const float* __restrict__ Wemit,
    const float* __restrict__ bemit,
    const float* __restrict__ start_tr,
    const float* __restrict__ trans,
    const float* __restrict__ end_tr,
    const int* __restrict__ lengths,
    const int* __restrict__ labels,
    float* __restrict__ out)
{
    __shared__ float4     sEnc[HH];       // (w0,w1,w2,w3)
    __shared__ ulonglong2 sEmA[HH];       // (e01, e23)
    __shared__ ulonglong2 sEmB[HH];       // (e45, e67)
    __shared__ ulonglong2 sEmC[HH];       // (e89, (e10, bn))
    __shared__ float      sEem[512*12];   // 24 KB: ee rows for this block's 512 tokens
    __shared__ float      sRedN[8], sRedD[8];

    int tid = threadIdx.x;
    int b = blockIdx.y;
    int t0 = blockIdx.x * 512;
    int len = lengths[b];

    if (blockIdx.x == 0 && b == 0 && tid == 0) out[0] = 0.f;

    // stage weights (256 threads, one pass)
    {
        int h = tid;
        sEnc[h] = make_float4(Wenc[h], Wenc[HH+h], Wenc[2*HH+h], Wenc[3*HH+h]);
        float e[11];
        #pragma unroll
        for (int q = 0; q < 11; q++) e[q] = Wemit[h*11+q];
        sEmA[h] = make_ulonglong2(pk2(e[0],e[1]), pk2(e[2],e[3]));
        sEmB[h] = make_ulonglong2(pk2(e[4],e[5]), pk2(e[6],e[7]));
        sEmC[h] = make_ulonglong2(pk2(e[8],e[9]), pk2(e[10], benc[h]));
    }
    __syncthreads();

    // ---- em phase: 2 tokens per thread (ta, ta+256) ----
    {
        int ta = t0 + tid;
        const float4* sq = (const float4*)seq + (size_t)b*TT;
        float4 x0 = sq[ta], x1 = sq[ta+256];

        ull b01 = pk2(bemit[0],bemit[1]);
        ull b23 = pk2(bemit[2],bemit[3]);
        ull b45 = pk2(bemit[4],bemit[5]);
        ull b67 = pk2(bemit[6],bemit[7]);
        ull b89 = pk2(bemit[8],bemit[9]);
        float b10 = bemit[10];

        ull a0[5] = {b01,b23,b45,b67,b89};
        ull a1[5] = {b01,b23,b45,b67,b89};
        ull aX = pk2(b10,b10);

        #pragma unroll 4
        for (int h = 0; h < HH; h++){
            float4 w = sEnc[h];
            ulonglong2 eA = sEmA[h];
            ulonglong2 eB = sEmB[h];
            ulonglong2 eC = sEmC[h];
            float e10, bn; upk2(e10, bn, eC.y);
            ull e89 = eC.x;
            ull eXX = pk2(e10, e10);

            float hd0 = fmaxf(fmaf(x0.x,w.x,fmaf(x0.y,w.y,fmaf(x0.z,w.z,fmaf(x0.w,w.w,bn)))), 0.f);
            float hd1 = fmaxf(fmaf(x1.x,w.x,fmaf(x1.y,w.y,fmaf(x1.z,w.z,fmaf(x1.w,w.w,bn)))), 0.f);

            ull p0 = pk2(hd0,hd0), p1 = pk2(hd1,hd1);

            a0[0]=ffma2(p0,eA.x,a0[0]); a0[1]=ffma2(p0,eA.y,a0[1]);
            a0[2]=ffma2(p0,eB.x,a0[2]); a0[3]=ffma2(p0,eB.y,a0[3]); a0[4]=ffma2(p0,e89,a0[4]);
            a1[0]=ffma2(p1,eA.x,a1[0]); a1[1]=ffma2(p1,eA.y,a1[1]);
            a1[2]=ffma2(p1,eB.x,a1[2]); a1[3]=ffma2(p1,eB.y,a1[3]); a1[4]=ffma2(p1,e89,a1[4]);

            aX = ffma2(pk2(hd0,hd1), eXX, aX);
        }

        float x10a, x10b;
        upk2(x10a, x10b, aX);

        float numc = 0.f, msks = 0.f;
        {
            float em[11];
            upk2(em[0],em[1],a0[0]); upk2(em[2],em[3],a0[1]); upk2(em[4],em[5],a0[2]);
            upk2(em[6],em[7],a0[3]); upk2(em[8],em[9],a0[4]); em[10]=x10a;
            process_token_sm(ta, tid, b, len, em, sEem, start_tr, trans, end_tr, labels, numc, msks);
        }
        {
            float em[11];
            upk2(em[0],em[1],a1[0]); upk2(em[2],em[3],a1[1]); upk2(em[4],em[5],a1[2]);
            upk2(em[6],em[7],a1[3]); upk2(em[8],em[9],a1[4]); em[10]=x10b;
            process_token_sm(ta+256, tid+256, b, len, em, sEem, start_tr, trans, end_tr, labels, numc, msks);
        }

        #pragma unroll
        for (int o = 16; o > 0; o >>= 1){
            numc += __shfl_xor_sync(0xffffffffu, numc, o);
            msks += __shfl_xor_sync(0xffffffffu, msks, o);
        }
        if ((tid & 31) == 0){ sRedN[tid >> 5] = numc; sRedD[tid >> 5] = msks; }
    }
    __syncthreads();   // sEem + sRedN/D complete

    if (tid == 0){
        float sn = 0.f, sd = 0.f;
        #pragma unroll
        for (int q = 0; q < 8; q++){ sn += sRedN[q]; sd += sRedD[q]; }
        g_numpart[b*NBLK + blockIdx.x] = sn;
        g_denpart[b*NBLK + blockIdx.x] = sd;
    }

    // ---- chunk phase: warp-autonomous 64-step scans (proven R15 code) ----
    int w = tid >> 5, l = tid & 31;
    int c = blockIdx.x * CWPB + w;
    int ct0 = c * LCH;

    int i = l % 11;
    int h = l / 11;          // 0 or 1 active; 2 for lanes 22..31
    bool act = l < 22;
    int hc = act ? h : 0;
    int j0 = h * 6;

    float Treg[6][11];
    #pragma unroll
    for (int jj = 0; jj < 6; jj++){
        int j = j0 + jj;
        int jcl = (act && j < 11) ? j : 0;
        float flag = (act && j < 11) ? 1.f : 0.f;
        #pragma unroll
        for (int k = 0; k < 11; k++)
            Treg[jj][k] = flag * __expf(trans[k*11 + jcl]);
    }

    float row[11];
    #pragma unroll
    for (int k = 0; k < 11; k++) row[k] = (act && k == i) ? 1.f : 0.f;

    int partner = act ? (h ? l - 11 : l + 11) : l;
    int eacc = 0;
    const float* emm = &sEem[w * LCH * 12];

    for (int s = 0; s < LCH; s++){
        int t = ct0 + s;
        bool valid = (t >= 1) && (t < len);     // warp-uniform
        if (valid){
            float4 A  = *(const float4*)&emm[s*12 + hc*8];
            float2 Bv = *(const float2*)&emm[s*12 + 4 + hc*2];
            float ee[6];
            if (hc == 0){ ee[0]=A.x; ee[1]=A.y; ee[2]=A.z; ee[3]=A.w; ee[4]=Bv.x; ee[5]=Bv.y; }
            else        { ee[0]=Bv.x; ee[1]=Bv.y; ee[2]=A.x; ee[3]=A.y; ee[4]=A.z; ee[5]=A.w; }

            float ns[6];
            #pragma unroll
            for (int jj = 0; jj < 6; jj++){
                float s2 = row[0]*Treg[jj][0];
                #pragma unroll
                for (int k = 1; k < 11; k++) s2 = fmaf(row[k], Treg[jj][k], s2);
                ns[jj] = s2 * ee[jj];
            }
            float other[6];
            #pragma unroll
            for (int q = 0; q < 6; q++) other[q] = __shfl_sync(0xffffffffu, ns[q], partner);
            if (h == 0){
                #pragma unroll
                for (int jj = 0; jj < 6; jj++) row[jj] = ns[jj];
                #pragma unroll
                for (int q = 0; q < 5; q++) row[6+q] = other[q];
            } else if (h == 1){
                #pragma unroll
                for (int q = 0; q < 6; q++) row[q] = other[q];
                #pragma unroll
                for (int jj = 0; jj < 5; jj++) row[6+jj] = ns[jj];
            }
        }
        if ((s & 7) == 7){
            float m = row[0];
            #pragma unroll
            for (int k = 1; k < 11; k++) m = fmaxf(m, row[k]);
            if (m > 0.f){
                int e = 0;
                frexpf(m, &e);
                float sc = exp2f((float)(-e));
                #pragma unroll
                for (int k = 0; k < 11; k++) row[k] *= sc;
                eacc += e;
            }
        }
    }

    int ev = act ? eacc : (-2147483647 - 1);
    #pragma unroll
    for (int o = 16; o > 0; o >>= 1) ev = max(ev, __shfl_xor_sync(0xffffffffu, ev, o));

    if (act){
        float sc = exp2f((float)(eacc - ev));
        size_t base = ((size_t)(b*KCH + c)) * MST + (size_t)i*12;
        if (h == 0){
            #pragma unroll
            for (int jj = 0; jj < 6; jj++) g_M[base + jj] = row[jj] * sc;
        } else {
            #pragma unroll
            for (int jj = 0; jj < 5; jj++) g_M[base + 6 + jj] = row[6+jj] * sc;
            g_M[base + 11] = 0.f;
        }
    }
    if (l == 0) g_exps[b*KCH + c] = ev;
}

// ---------------------------------------------------------------------------
// Kernel 2 (tail): per-batch 7-level tree over 128 chunk matrices in SMEM.
// Grid BB, 512 threads, 101 KB dynamic smem. (Proven R13/R15.)
// ---------------------------------------------------------------------------
__global__ void __launch_bounds__(512) tail_kernel(
    const float* __restrict__ start_tr,
    const float* __restrict__ end_tr,
    float* __restrict__ out)
{
    extern __shared__ float dynsm[];
    float* bufA = dynsm;
    float* bufB = dynsm + 128*MST;
    __shared__ float sRedM[16];
    __shared__ float sNum, sDen;
    __shared__ int   sExp;

    int tid = threadIdx.x;
    int b = blockIdx.x;

    if (tid == 0){ sNum = 0.f; sDen = 0.f; sExp = 0; }
    __syncthreads();

    {
        const float4* src = (const float4*)&g_M[(size_t)b*KCH*MST];
        for (int q = tid; q < 128*MST/4; q += 512) ((float4*)bufA)[q] = src[q];
    }

    {
        float nacc = 0.f, dacc = 0.f; int eacc = 0;
        if (tid < NBLK){ nacc = g_numpart[b*NBLK + tid]; dacc = g_denpart[b*NBLK + tid]; }
        if (tid < KCH)  eacc = g_exps[b*KCH + tid];
        #pragma unroll
        for (int o = 16; o > 0; o >>= 1){
            nacc += __shfl_xor_sync(0xffffffffu, nacc, o);
            dacc += __shfl_xor_sync(0xffffffffu, dacc, o);
            eacc += __shfl_xor_sync(0xffffffffu, eacc, o);
        }
        if ((tid & 31) == 0 && tid < KCH){
            atomicAdd(&sNum, nacc);
            atomicAdd(&sDen, dacc);
            atomicAdd(&sExp, eacc);
        }
    }
    __syncthreads();

    int unit = tid >> 7, st = tid & 127;
    int i = st / 11, j = st - i*11;
    bool act = st < 121;
    int wiu = st >> 5;

    for (int q = unit; q < 64; q += 4)
        if (act) storeP(&bufB[q*MST], i, j, mm11(&bufA[(2*q)*MST], &bufA[(2*q+1)*MST], i, j));
    __syncthreads();
    for (int q = unit; q < 32; q += 4)
        if (act) storeP(&bufA[q*MST], i, j, mm11(&bufB[(2*q)*MST], &bufB[(2*q+1)*MST], i, j));
    __syncthreads();
    for (int q = unit; q < 16; q += 4)
        if (act) storeP(&bufB[q*MST], i, j, mm11(&bufA[(2*q)*MST], &bufA[(2*q+1)*MST], i, j));
    __syncthreads();
    #pragma unroll
    for (int r = 0; r < 2; r++){
        int q = r*4 + unit;
        float v = act ? mm11(&bufB[(2*q)*MST], &bufB[(2*q+1)*MST], i, j) : 0.f;
        float m = v;
        #pragma unroll
        for (int o = 16; o > 0; o >>= 1) m = fmaxf(m, __shfl_xor_sync(0xffffffffu, m, o));
        if ((st & 31) == 0) sRedM[unit*4 + wiu] = m;
        __syncthreads();
        float mxv = fmaxf(fmaxf(sRedM[unit*4], sRedM[unit*4+1]), fmaxf(sRedM[unit*4+2], sRedM[unit*4+3]));
        int e = 0; frexpf(mxv, &e);
        if (act) storeP(&bufA[q*MST], i, j, v * exp2f((float)(-e)));
        if (st == 0) atomicAdd(&sExp, e);
        __syncthreads();
    }
    {
        int q = unit;
        if (act) storeP(&bufB[q*MST], i, j, mm11(&bufA[(2*q)*MST], &bufA[(2*q+1)*MST], i, j));
    }
    __syncthreads();
    {
        bool run = unit < 2;
        float v = (run && act) ? mm11(&bufB[(2*unit)*MST], &bufB[(2*unit+1)*MST], i, j) : 0.f;
        float m = v;
        #pragma unroll
        for (int o = 16; o > 0; o >>= 1) m = fmaxf(m, __shfl_xor_sync(0xffffffffu, m, o));
        if ((st & 31) == 0) sRedM[unit*4 + wiu] = m;
        __syncthreads();
        float mxv = fmaxf(fmaxf(sRedM[unit*4], sRedM[unit*4+1]), fmaxf(sRedM[unit*4+2], sRedM[unit*4+3]));
        int e = 0; frexpf(mxv, &e);
        if (run && act) storeP(&bufA[unit*MST], i, j, v * exp2f((float)(-e)));
        if (run && st == 0) atomicAdd(&sExp, e);
        __syncthreads();
    }
    if (unit == 0 && act)
        storeP(&bufB[0], i, j, mm11(&bufA[0], &bufA[MST], i, j));
    __syncthreads();

    if (tid < 32){
        bool a11 = tid < 11;
        float p0 = a11 ? __expf(start_tr[tid]) * g_a0[b*12 + tid] : 0.f;
        float pf = 0.f;
        #pragma unroll
        for (int k = 0; k < 11; k++){
            float pkv = __shfl_sync(0xffffffffu, p0, k);
            pf = fmaf(pkv, a11 ? bufB[k*12 + tid] : 0.f, pf);
        }
        float vv = a11 ? pf * __expf(end_tr[tid]) : 0.f;
        #pragma unroll
        for (int o = 16; o > 0; o >>= 1) vv += __shfl_xor_sync(0xffffffffu, vv, o);
        if (tid == 0){
            float den = logf(vv) + 0.6931471805599453f * (float)sExp + sDen;
            atomicAdd(out, (den - sNum) * (1.0f / (float)BB));
        }
    }
}

// ---------------------------------------------------------------------------
// Launch
// ---------------------------------------------------------------------------
#define SMEM_TAIL ((128*MST + 64*MST) * 4)

extern "C" void kernel_launch(void* const* d_in, const int* in_sizes, int n_in,
                              void* d_out, int out_size)
{
    const float* seq      = (const float*)d_in[0];
    const float* Wenc     = (const float*)d_in[1];
    const float* benc     = (const float*)d_in[2];
    const float* Wemit    = (const float*)d_in[3];
    const float* bemit    = (const float*)d_in[4];
    const float* start_tr = (const float*)d_in[5];
    const float* trans    = (const float*)d_in[6];
    const float* end_tr   = (const float*)d_in[7];
    const int* lengths    = (const int*)d_in[8];
    const int* labels     = (const int*)d_in[9];
    float* out = (float*)d_out;

    cudaFuncSetAttribute(tail_kernel, cudaFuncAttributeMaxDynamicSharedMemorySize, SMEM_TAIL);

    fused_kernel<<<dim3(NBLK, BB), 256>>>(seq, Wenc, benc, Wemit, bemit,
                                          start_tr, trans, end_tr, lengths, labels, out);
    tail_kernel<<<BB, 512, SMEM_TAIL>>>(start_tr, end_tr, out);
}